// round 4
// baseline (speedup 1.0000x reference)
#include <cuda_runtime.h>
#include <cuda.h>
#include <cstdint>

// LZC48 over binary float spikes: [n_words, 48] f32 {0,1} -> [n_words, 6] f32.
//
// R4 (= R3 retest after infra failure): TMA sector gather. LDG misses get
// promoted to 128B line fills at L2 (measured ~122 B/word vs 32 B requested).
// TMA tensor maps carry a per-descriptor L2-promotion field; with
// CU_TENSOR_MAP_L2_PROMOTION_NONE a 2D box {8,256} gathers each word's 32B
// prefix sector without line promotion. Fallback full scan (P=1/256 per word)
// via plain LDG; LDG-only kernel if the tensor map can't be built.

constexpr int TPB = 256;
constexpr int WPB = 512;                  // words per block tile
constexpr unsigned TILE_BYTES = WPB * 32; // 16384

// ---------------------------------------------------------------- TMA kernel
__global__ __launch_bounds__(TPB)
void lzc48_tma_kernel(const __grid_constant__ CUtensorMap tmap,
                      const uint4* __restrict__ in4,   // raw input, for fallback
                      float* __restrict__ out,
                      int n_words)
{
    __shared__ __align__(128) uint4 tile[WPB * 2];   // 512 words x 32B prefix
    __shared__ float sout[WPB * 6];
    __shared__ __align__(8) unsigned long long mbar;

    const int t = threadIdx.x;
    const int tile0 = blockIdx.x * WPB;
    int count = n_words - tile0;
    if (count > WPB) count = WPB;

    const unsigned mb = (unsigned)__cvta_generic_to_shared(&mbar);

    if (t == 0) {
        asm volatile("mbarrier.init.shared::cta.b64 [%0], 1;" :: "r"(mb) : "memory");
        asm volatile("mbarrier.arrive.expect_tx.shared::cta.b64 _, [%0], %1;"
                     :: "r"(mb), "r"(TILE_BYTES) : "memory");
        const CUtensorMap* tp = &tmap;
        unsigned s0 = (unsigned)__cvta_generic_to_shared(&tile[0]);
        unsigned s1 = (unsigned)__cvta_generic_to_shared(&tile[512]);
        asm volatile("cp.async.bulk.tensor.2d.shared::cta.global.tile.mbarrier::complete_tx::bytes "
                     "[%0], [%1, {%2, %3}], [%4];"
                     :: "r"(s0), "l"(tp), "r"(0), "r"(tile0), "r"(mb) : "memory");
        asm volatile("cp.async.bulk.tensor.2d.shared::cta.global.tile.mbarrier::complete_tx::bytes "
                     "[%0], [%1, {%2, %3}], [%4];"
                     :: "r"(s1), "l"(tp), "r"(0), "r"(tile0 + 256), "r"(mb) : "memory");
    }
    __syncthreads();   // mbar init + expect_tx visible before polling

    // Wait for both TMA completions (phase 0). try_wait defaults to acquire.
    {
        unsigned done;
        asm volatile(
            "{\n\t.reg .pred p;\n\t"
            "mbarrier.try_wait.parity.shared::cta.b64 p, [%1], %2;\n\t"
            "selp.b32 %0, 1, 0, p;\n\t}"
            : "=r"(done) : "r"(mb), "r"(0u) : "memory");
        while (!done) {
            asm volatile(
                "{\n\t.reg .pred p;\n\t"
                "mbarrier.try_wait.parity.shared::cta.b64 p, [%1], %2, 0x989680;\n\t"
                "selp.b32 %0, 1, 0, p;\n\t}"
                : "=r"(done) : "r"(mb), "r"(0u) : "memory");
        }
    }

    // ---- decode 2 words per thread ----
    #pragma unroll
    for (int k = 0; k < 2; k++) {
        const int wl = t + k * TPB;              // word index within tile
        if (wl >= count) break;
        uint4 e = tile[wl * 2];
        uint4 o = tile[wl * 2 + 1];
        unsigned m = (e.x ? 128u : 0u) | (e.y ? 64u : 0u) | (e.z ? 32u : 0u) | (e.w ? 16u : 0u)
                   | (o.x ?   8u : 0u) | (o.y ?  4u : 0u) | (o.z ?  2u : 0u) | (o.w ?  1u : 0u);
        int lzc;
        if (m) {
            lzc = __clz(m << 24);
        } else {
            const uint4* wp = in4 + (size_t)(tile0 + wl) * 12;
            unsigned long long acc = 0ull;
            #pragma unroll
            for (int i = 2; i < 12; i++) {
                uint4 v = __ldcg(wp + i);
                unsigned nib = (v.x ? 8u : 0u) | (v.y ? 4u : 0u)
                             | (v.z ? 2u : 0u) | (v.w ? 1u : 0u);
                acc = (acc << 4) | nib;
            }
            lzc = acc ? (8 + __clzll(acc << 24)) : 48;
        }
        float* so = sout + wl * 6;
        so[0] = (float)((lzc >> 5) & 1);
        so[1] = (float)((lzc >> 4) & 1);
        so[2] = (float)((lzc >> 3) & 1);
        so[3] = (float)((lzc >> 2) & 1);
        so[4] = (float)((lzc >> 1) & 1);
        so[5] = (float)( lzc       & 1);
    }
    __syncthreads();

    // ---- coalesced output: 512*6 floats = 768 float4 ----
    if (count == WPB) {
        float4* ob = reinterpret_cast<float4*>(out + (size_t)tile0 * 6);
        const float4* sb = reinterpret_cast<const float4*>(sout);
        #pragma unroll
        for (int k = 0; k < 3; k++)
            ob[k * TPB + t] = sb[k * TPB + t];
    } else {
        for (int j = t; j < count * 6; j += TPB)
            out[(size_t)tile0 * 6 + j] = sout[j];
    }
}

// ------------------------------------------------------------ fallback (R1)
__global__ __launch_bounds__(TPB)
void lzc48_ldg_kernel(const uint4* __restrict__ in4, float* __restrict__ out,
                      int n_words)
{
    __shared__ uint4 sbuf[520];
    __shared__ float sout[256 * 6];

    const int tile = blockIdx.x * 256;
    int count = n_words - tile;
    if (count > 256) count = 256;

    #pragma unroll
    for (int k = 0; k < 2; k++) {
        int j = k * TPB + threadIdx.x;
        int w = j >> 1, h = j & 1;
        if (w < count)
            sbuf[(h ? 260 : 0) + w] = in4[(size_t)(tile + w) * 12 + h];
    }
    __syncthreads();

    const int t = threadIdx.x;
    if (t < count) {
        uint4 e = sbuf[t], o = sbuf[260 + t];
        unsigned m = (e.x ? 128u : 0u) | (e.y ? 64u : 0u) | (e.z ? 32u : 0u) | (e.w ? 16u : 0u)
                   | (o.x ?   8u : 0u) | (o.y ?  4u : 0u) | (o.z ?  2u : 0u) | (o.w ?  1u : 0u);
        int lzc;
        if (m) lzc = __clz(m << 24);
        else {
            const uint4* wp = in4 + (size_t)(tile + t) * 12;
            unsigned long long acc = 0ull;
            #pragma unroll
            for (int i = 2; i < 12; i++) {
                uint4 v = wp[i];
                unsigned nib = (v.x ? 8u : 0u) | (v.y ? 4u : 0u)
                             | (v.z ? 2u : 0u) | (v.w ? 1u : 0u);
                acc = (acc << 4) | nib;
            }
            lzc = acc ? (8 + __clzll(acc << 24)) : 48;
        }
        float* so = sout + t * 6;
        so[0] = (float)((lzc >> 5) & 1); so[1] = (float)((lzc >> 4) & 1);
        so[2] = (float)((lzc >> 3) & 1); so[3] = (float)((lzc >> 2) & 1);
        so[4] = (float)((lzc >> 1) & 1); so[5] = (float)( lzc       & 1);
    }
    __syncthreads();

    if (count == 256) {
        float4* ob = reinterpret_cast<float4*>(out + (size_t)tile * 6);
        const float4* sb = reinterpret_cast<const float4*>(sout);
        ob[t] = sb[t];
        if (t < 128) ob[TPB + t] = sb[TPB + t];
    } else {
        for (int j = t; j < count * 6; j += TPB)
            out[(size_t)tile * 6 + j] = sout[j];
    }
}

// ----------------------------------------------------------------- launcher
typedef CUresult (*EncodeTiledFn)(
    CUtensorMap*, CUtensorMapDataType, cuuint32_t, void*,
    const cuuint64_t*, const cuuint64_t*, const cuuint32_t*, const cuuint32_t*,
    CUtensorMapInterleave, CUtensorMapSwizzle, CUtensorMapL2promotion,
    CUtensorMapFloatOOBfill);

static EncodeTiledFn get_encode_fn()
{
    void* fn = nullptr;
    cudaDriverEntryPointQueryResult qres = cudaDriverEntryPointSymbolNotFound;
    if (cudaGetDriverEntryPointByVersion("cuTensorMapEncodeTiled", &fn, 12000,
                                         cudaEnableDefault, &qres) == cudaSuccess
        && qres == cudaDriverEntryPointSuccess && fn)
        return (EncodeTiledFn)fn;
    fn = nullptr;
    qres = cudaDriverEntryPointSymbolNotFound;
    if (cudaGetDriverEntryPoint("cuTensorMapEncodeTiled", &fn,
                                cudaEnableDefault, &qres) == cudaSuccess
        && qres == cudaDriverEntryPointSuccess && fn)
        return (EncodeTiledFn)fn;
    return nullptr;
}

extern "C" void kernel_launch(void* const* d_in, const int* in_sizes, int n_in,
                              void* d_out, int out_size)
{
    const uint4* in4 = (const uint4*)d_in[0];
    float* out = (float*)d_out;
    const int n_words = in_sizes[0] / 48;   // 2,097,152

    // Build the tensor map on every call (deterministic, host-only work).
    bool tma_ok = false;
    CUtensorMap tmap;
    EncodeTiledFn encode = get_encode_fn();
    if (encode) {
        cuuint64_t dims[2]    = { 48, (cuuint64_t)n_words };
        cuuint64_t strides[1] = { 192 };                 // bytes per word row
        cuuint32_t box[2]     = { 8, 256 };              // 32B prefix x 256 words
        cuuint32_t estr[2]    = { 1, 1 };
        CUresult r = encode(&tmap, CU_TENSOR_MAP_DATA_TYPE_FLOAT32, 2,
                            (void*)in4, dims, strides, box, estr,
                            CU_TENSOR_MAP_INTERLEAVE_NONE,
                            CU_TENSOR_MAP_SWIZZLE_NONE,
                            CU_TENSOR_MAP_L2_PROMOTION_NONE,
                            CU_TENSOR_MAP_FLOAT_OOB_FILL_NONE);
        tma_ok = (r == CUDA_SUCCESS);
    }

    if (tma_ok) {
        const int grid = (n_words + WPB - 1) / WPB;          // 4096
        lzc48_tma_kernel<<<grid, TPB>>>(tmap, in4, out, n_words);
    } else {
        const int grid = (n_words + 255) / 256;              // 8192
        lzc48_ldg_kernel<<<grid, TPB>>>(in4, out, n_words);
    }
}